// round 14
// baseline (speedup 1.0000x reference)
#include <cuda_runtime.h>
#include <math.h>

// Problem constants
#define NPATCH     8
#define BINS       256
#define IMG_H      1024
#define IMG_W      1024
#define NBC        48            // B*C = 16*3
#define PH         128           // patch height
#define PW         128           // patch width
#define SEGS       6144          // NBC * PH row-segments per patch
#define CHUNKS     32            // blocks per patch
#define TOTAL_ELEMS 50331648.0   // 16*3*1024*1024

// XLA algsimp folds divide-by-constant -> multiply-by-f32-reciprocal.
__device__ __constant__ float RECIP_N   = 1.0f / 786432.0f;   // 0x35AAAAAB
__device__ __constant__ float RECIP_LN2 = 1.442695040888963f; // fl(1/fl(ln2)) = 0x3FB8AA3B

// Scratch (no allocation allowed in kernel_launch)
__device__ unsigned int g_hist[64 * BINS];
__device__ double       g_psum[64];

__global__ void zero_kernel() {
    int i = blockIdx.x * blockDim.x + threadIdx.x;
    if (i < 64 * BINS) g_hist[i] = 0u;
    if (i < 64)        g_psum[i] = 0.0;
}

// One block = (patch, chunk). 256 threads, 8 warps.
// Each warp processes whole 128-float row segments: lane -> float4.
__global__ __launch_bounds__(256)
void hist_kernel(const float* __restrict__ sr, const float* __restrict__ hr) {
    __shared__ unsigned int sh_hist[BINS];
    __shared__ float        sh_psum;

    const int tid = threadIdx.x;
    if (tid < BINS) sh_hist[tid] = 0u;
    if (tid == 0)   sh_psum = 0.0f;
    __syncthreads();

    const int patch = blockIdx.x >> 5;     // 0..63
    const int chunk = blockIdx.x & (CHUNKS - 1);
    const int pr = patch >> 3;             // patch row (height)
    const int pc = patch & 7;              // patch col (width)
    const int warp = tid >> 5;
    const int lane = tid & 31;

    const size_t col = (size_t)pc * PW + (size_t)lane * 4;
    float acc = 0.0f;

    // 6144 segments / 256 warps-per-patch-in-grid = 24 iterations, balanced
    for (int s = chunk * 8 + warp; s < SEGS; s += CHUNKS * 8) {
        const int bc = s >> 7;         // which (b,c) plane
        const int r  = s & 127;        // row within patch
        const size_t base =
            (((size_t)bc * IMG_H) + (size_t)pr * PH + r) * (size_t)IMG_W + col;

        const float4 h  = *reinterpret_cast<const float4*>(hr + base);
        const float4 sv = *reinterpret_cast<const float4*>(sr + base);

        // (h * 255.0f) f32 multiply, truncate toward zero — bit-identical to
        // (patches * 255.0).astype(int32). Values in [0,1) -> bins 0..254.
        int b0 = (int)(h.x * 255.0f);
        int b1 = (int)(h.y * 255.0f);
        int b2 = (int)(h.z * 255.0f);
        int b3 = (int)(h.w * 255.0f);

        atomicAdd(&sh_hist[b0], 1u);
        atomicAdd(&sh_hist[b1], 1u);
        atomicAdd(&sh_hist[b2], 1u);
        atomicAdd(&sh_hist[b3], 1u);

        acc += fabsf(sv.x - h.x) + fabsf(sv.y - h.y)
             + fabsf(sv.z - h.z) + fabsf(sv.w - h.w);
    }

    // warp tree-reduce abs-diff partial
    #pragma unroll
    for (int o = 16; o > 0; o >>= 1)
        acc += __shfl_down_sync(0xffffffffu, acc, o);
    if (lane == 0) atomicAdd(&sh_psum, acc);
    __syncthreads();

    // merge block-private results into globals
    if (tid < BINS) {
        unsigned int c = sh_hist[tid];
        if (c) atomicAdd(&g_hist[patch * BINS + tid], c);
    }
    if (tid == 0) atomicAdd(&g_psum[patch], (double)sh_psum);
}

// Per-element term — VALIDATED in R13 (do not change):
//   p = c * fl(1/786432); l2 = logf(p) * fl(1/ln2); term = p * l2
//   (separate f32 muls, no FMA); zero-count bins -> exact 0.0f.
__device__ __forceinline__ float ent_term(unsigned int c) {
    float pf   = __fmul_rn((float)c, RECIP_N);
    float safe = (c > 0u) ? pf : 1.0f;
    float l2   = __fmul_rn(logf(safe), RECIP_LN2);
    return (c > 0u) ? __fmul_rn(pf, l2) : 0.0f;
}

// Fused entropy + loss: ONE block of 1024 threads.
// Entropy uses the VALIDATED R13 association per patch (flat 256-thread
// row reduce): thread-group of 256 handles one patch; 4 patches per pass,
// 16 passes. Per patch: acc = 0 + e_bin; per-warp shfl.down tree over 32
// consecutive bins; 8 warp partials; first warp of the group: v = lane<8 ?
// P[lane] : 0, full shfl tree. Bit-identical to R13's entropy_kernel.
// Then: parallel min/max over the 64 f32 entropies and a parallel f64
// weighted sum of the patch abs-diff sums (f64 order-insensitive here).
__global__ __launch_bounds__(1024)
void final_kernel(float* __restrict__ out) {
    __shared__ float  partials[4][8];
    __shared__ float  ent[64];
    __shared__ float  red32[32];
    __shared__ double redd[32];

    const int t     = threadIdx.x;
    const int lane  = t & 31;
    const int warp  = t >> 5;       // 0..31
    const int grp   = t >> 8;       // 0..3  patch subgroup
    const int gwarp = warp & 7;     // warp within subgroup
    const int bin   = t & 255;

    #pragma unroll 1
    for (int it = 0; it < 16; it++) {
        const int p = grp + 4 * it;          // patch id
        float acc = __fadd_rn(0.0f, ent_term(g_hist[p * BINS + bin]));
        #pragma unroll
        for (int o = 16; o > 0; o >>= 1)
            acc = __fadd_rn(acc, __shfl_down_sync(0xffffffffu, acc, o));
        if (lane == 0) partials[grp][gwarp] = acc;
        __syncthreads();
        if (gwarp == 0) {
            float v = (lane < 8) ? partials[grp][lane] : 0.0f;
            #pragma unroll
            for (int o = 16; o > 0; o >>= 1)
                v = __fadd_rn(v, __shfl_down_sync(0xffffffffu, v, o));
            if (lane == 0) ent[p] = -v;      // negate after the sum
        }
        __syncthreads();
    }

    // ---- parallel min/max over 64 entropies (order-independent) ----
    float e  = (t < 64) ? ent[t] : ent[0];
    float mnv = e, mxv = e;
    if (t < 64) {
        #pragma unroll
        for (int o = 16; o > 0; o >>= 1) {
            mnv = fminf(mnv, __shfl_down_sync(0xffffffffu, mnv, o));
            mxv = fmaxf(mxv, __shfl_down_sync(0xffffffffu, mxv, o));
        }
        if (lane == 0) { red32[warp] = mnv; red32[warp + 16] = mxv; }
    }
    __syncthreads();
    __shared__ float s_mn, s_mx;
    if (t == 0) {
        s_mn = fminf(red32[0], red32[1]);
        s_mx = fmaxf(red32[16], red32[17]);
    }
    __syncthreads();
    const float mn = s_mn, mx = s_mx;

    // ---- parallel weighted loss: sum_i w_i * S_i in f64 ----
    double prod = 0.0;
    if (t < 64) {
        // weight in f32 exactly as the reference map: (e - mn) / original max
        float w = __fdiv_rn(__fadd_rn(ent[t], -mn), mx);
        prod = (double)w * g_psum[t];
    }
    if (t < 64) {
        #pragma unroll
        for (int o = 16; o > 0; o >>= 1)
            prod += __shfl_down_sync(0xffffffffu, prod, o);
        if (lane == 0) redd[warp] = prod;
    }
    __syncthreads();
    if (t == 0) {
        double loss = redd[0] + redd[1];
        out[0] = (float)(loss / TOTAL_ELEMS);
    }
}

extern "C" void kernel_launch(void* const* d_in, const int* in_sizes, int n_in,
                              void* d_out, int out_size) {
    const float* sr = (const float*)d_in[0];
    const float* hr = (const float*)d_in[1];
    float* out = (float*)d_out;
    (void)in_sizes; (void)n_in; (void)out_size;

    zero_kernel<<<(64 * BINS + 255) / 256, 256>>>();
    hist_kernel<<<64 * CHUNKS, 256>>>(sr, hr);
    final_kernel<<<1, 1024>>>(out);
}

// round 15
// speedup vs baseline: 1.0786x; 1.0786x over previous
#include <cuda_runtime.h>
#include <math.h>

// Problem constants
#define NPATCH     8
#define BINS       256
#define IMG_H      1024
#define IMG_W      1024
#define NBC        48            // B*C = 16*3
#define PH         128           // patch height
#define PW         128           // patch width
#define SEGS       6144          // NBC * PH row-segments per patch
#define CHUNKS     32            // blocks per patch
#define NBLK       (64 * CHUNKS) // 2048 hist blocks
#define TOTAL_ELEMS 50331648.0   // 16*3*1024*1024

// XLA algsimp folds divide-by-constant -> multiply-by-f32-reciprocal.
__device__ __constant__ float RECIP_N   = 1.0f / 786432.0f;   // 0x35AAAAAB
__device__ __constant__ float RECIP_LN2 = 1.442695040888963f; // fl(1/fl(ln2)) = 0x3FB8AA3B

// Scratch (no allocation allowed in kernel_launch). Plain-store partials —
// every slot is overwritten each run, so NO zero kernel is needed.
__device__ unsigned int g_hist_part[NBLK * BINS];   // 2 MB, L2-resident
__device__ float        g_psum_part[NBLK];
__device__ float        g_ent[64];

// One block = (patch, chunk). 256 threads, 8 warps.
// Each warp processes whole 128-float row segments: lane -> float4.
// Ends with PLAIN coalesced stores of the block-private results.
__global__ __launch_bounds__(256)
void hist_kernel(const float* __restrict__ sr, const float* __restrict__ hr) {
    __shared__ unsigned int sh_hist[BINS];
    __shared__ float        sh_psum;

    const int tid = threadIdx.x;
    if (tid < BINS) sh_hist[tid] = 0u;
    if (tid == 0)   sh_psum = 0.0f;
    __syncthreads();

    const int patch = blockIdx.x >> 5;     // 0..63
    const int chunk = blockIdx.x & (CHUNKS - 1);
    const int pr = patch >> 3;             // patch row (height)
    const int pc = patch & 7;              // patch col (width)
    const int warp = tid >> 5;
    const int lane = tid & 31;

    const size_t col = (size_t)pc * PW + (size_t)lane * 4;
    float acc = 0.0f;

    // 6144 segments / 256 warps-per-patch-in-grid = 24 iterations, balanced
    for (int s = chunk * 8 + warp; s < SEGS; s += CHUNKS * 8) {
        const int bc = s >> 7;         // which (b,c) plane
        const int r  = s & 127;        // row within patch
        const size_t base =
            (((size_t)bc * IMG_H) + (size_t)pr * PH + r) * (size_t)IMG_W + col;

        const float4 h  = *reinterpret_cast<const float4*>(hr + base);
        const float4 sv = *reinterpret_cast<const float4*>(sr + base);

        // (h * 255.0f) f32 multiply, truncate toward zero — bit-identical to
        // (patches * 255.0).astype(int32). Values in [0,1) -> bins 0..254.
        int b0 = (int)(h.x * 255.0f);
        int b1 = (int)(h.y * 255.0f);
        int b2 = (int)(h.z * 255.0f);
        int b3 = (int)(h.w * 255.0f);

        atomicAdd(&sh_hist[b0], 1u);
        atomicAdd(&sh_hist[b1], 1u);
        atomicAdd(&sh_hist[b2], 1u);
        atomicAdd(&sh_hist[b3], 1u);

        acc += fabsf(sv.x - h.x) + fabsf(sv.y - h.y)
             + fabsf(sv.z - h.z) + fabsf(sv.w - h.w);
    }

    // warp tree-reduce abs-diff partial
    #pragma unroll
    for (int o = 16; o > 0; o >>= 1)
        acc += __shfl_down_sync(0xffffffffu, acc, o);
    if (lane == 0) atomicAdd(&sh_psum, acc);
    __syncthreads();

    // plain stores — no global atomics, no pre-zeroing required
    if (tid < BINS) g_hist_part[blockIdx.x * BINS + tid] = sh_hist[tid];
    if (tid == 0)   g_psum_part[blockIdx.x] = sh_psum;
}

// Per-element term — VALIDATED in R13 (do not change):
//   p = c * fl(1/786432); l2 = logf(p) * fl(1/ln2); term = p * l2
//   (separate f32 muls, no FMA); zero-count bins -> exact 0.0f.
__device__ __forceinline__ float ent_term(unsigned int c) {
    float pf   = __fmul_rn((float)c, RECIP_N);
    float safe = (c > 0u) ? pf : 1.0f;
    float l2   = __fmul_rn(logf(safe), RECIP_LN2);
    return (c > 0u) ? __fmul_rn(pf, l2) : 0.0f;
}

// VALIDATED R13 association (do not change): one block of 256 threads per
// patch. Thread = bin; integer chunk-partials summed exactly first (counts
// are exact integers, association-free). Then: acc = 0 + e_bin; per-warp
// shfl.down tree over 32 consecutive bins; 8 warp partials; warp 0:
// v = lane<8 ? P[lane] : 0, full shfl tree -> -sum.
__global__ __launch_bounds__(256)
void entropy_kernel() {
    __shared__ float partials[8];
    const int p    = blockIdx.x;       // patch 0..63
    const int t    = threadIdx.x;      // 0..255 = bin
    const int lane = t & 31;
    const int warp = t >> 5;

    unsigned int c = 0u;
    const unsigned int* part = &g_hist_part[(p * CHUNKS) * BINS + t];
    #pragma unroll
    for (int k = 0; k < CHUNKS; k++)
        c += part[k * BINS];

    float acc = __fadd_rn(0.0f, ent_term(c));

    #pragma unroll
    for (int o = 16; o > 0; o >>= 1)
        acc = __fadd_rn(acc, __shfl_down_sync(0xffffffffu, acc, o));
    if (lane == 0) partials[warp] = acc;
    __syncthreads();

    if (warp == 0) {
        float v = (lane < 8) ? partials[lane] : 0.0f;
        #pragma unroll
        for (int o = 16; o > 0; o >>= 1)
            v = __fadd_rn(v, __shfl_down_sync(0xffffffffu, v, o));
        if (lane == 0) g_ent[p] = -v;   // negate after the sum, like the ref
    }
}

// Loss: ONE block, 1024 threads, fully parallel.
// Warp w reduces patch w and w+32: lane l loads that patch's chunk-l psum
// partial (one load per lane), f64 shfl tree -> S_p. Then parallel min/max
// over the 64 f32 entropies and a parallel f64 weighted sum.
__global__ __launch_bounds__(1024)
void loss_kernel(float* __restrict__ out) {
    __shared__ double Ssum[64];
    __shared__ float  ent[64];
    __shared__ float  red32[32];
    __shared__ double redd[2];

    const int t    = threadIdx.x;
    const int lane = t & 31;
    const int warp = t >> 5;        // 0..31

    #pragma unroll
    for (int half = 0; half < 2; half++) {
        const int p = warp + 32 * half;
        double v = (double)g_psum_part[p * CHUNKS + lane];
        #pragma unroll
        for (int o = 16; o > 0; o >>= 1)
            v += __shfl_down_sync(0xffffffffu, v, o);
        if (lane == 0) Ssum[p] = v;
    }
    if (t < 64) ent[t] = g_ent[t];
    __syncthreads();

    // ---- parallel min/max over 64 entropies (order-independent) ----
    if (t < 64) {
        float mnv = ent[t], mxv = ent[t];
        #pragma unroll
        for (int o = 16; o > 0; o >>= 1) {
            mnv = fminf(mnv, __shfl_down_sync(0xffffffffu, mnv, o));
            mxv = fmaxf(mxv, __shfl_down_sync(0xffffffffu, mxv, o));
        }
        if (lane == 0) { red32[warp] = mnv; red32[warp + 16] = mxv; }
    }
    __syncthreads();
    __shared__ float s_mn, s_mx;
    if (t == 0) {
        s_mn = fminf(red32[0], red32[1]);
        s_mx = fmaxf(red32[16], red32[17]);
    }
    __syncthreads();
    const float mn = s_mn, mx = s_mx;

    // ---- parallel weighted loss: sum_i w_i * S_i in f64 ----
    if (t < 64) {
        // weight in f32 exactly as the reference map: (e - mn) / original max
        float w = __fdiv_rn(__fadd_rn(ent[t], -mn), mx);
        double prod = (double)w * Ssum[t];
        #pragma unroll
        for (int o = 16; o > 0; o >>= 1)
            prod += __shfl_down_sync(0xffffffffu, prod, o);
        if (lane == 0) redd[warp] = prod;
    }
    __syncthreads();
    if (t == 0)
        out[0] = (float)((redd[0] + redd[1]) / TOTAL_ELEMS);
}

extern "C" void kernel_launch(void* const* d_in, const int* in_sizes, int n_in,
                              void* d_out, int out_size) {
    const float* sr = (const float*)d_in[0];
    const float* hr = (const float*)d_in[1];
    float* out = (float*)d_out;
    (void)in_sizes; (void)n_in; (void)out_size;

    hist_kernel<<<NBLK, 256>>>(sr, hr);
    entropy_kernel<<<64, 256>>>();
    loss_kernel<<<1, 1024>>>(out);
}

// round 16
// speedup vs baseline: 1.0800x; 1.0013x over previous
#include <cuda_runtime.h>
#include <math.h>

// Problem constants
#define NPATCH     8
#define BINS       256
#define IMG_H      1024
#define IMG_W      1024
#define NBC        48            // B*C = 16*3
#define PH         128           // patch height
#define PW         128           // patch width
#define SEGS       6144          // NBC * PH row-segments per patch
#define CHUNKS     32            // blocks per patch
#define NBLK       (64 * CHUNKS) // 2048 hist blocks
#define ITERS      (SEGS / (CHUNKS * 8))   // 24, uniform across warps
#define TOTAL_ELEMS 50331648.0   // 16*3*1024*1024

// XLA algsimp folds divide-by-constant -> multiply-by-f32-reciprocal.
__device__ __constant__ float RECIP_N   = 1.0f / 786432.0f;   // 0x35AAAAAB
__device__ __constant__ float RECIP_LN2 = 1.442695040888963f; // fl(1/fl(ln2)) = 0x3FB8AA3B

// Scratch (no allocation allowed in kernel_launch). Plain-store partials —
// every slot is overwritten each run, so NO zero kernel is needed.
__device__ unsigned int g_hist_part[NBLK * BINS];   // 2 MB, L2-resident
__device__ float        g_psum_part[NBLK];
__device__ float        g_ent[64];
__device__ unsigned int g_done;                     // reset by hist_kernel

// One block = (patch, chunk). 256 threads, 8 warps.
// Each warp processes whole 128-float row segments: lane -> float4.
// unroll 2 -> 4 independent float4 loads in flight (higher MLP vs atomics).
__global__ __launch_bounds__(256)
void hist_kernel(const float* __restrict__ sr, const float* __restrict__ hr) {
    __shared__ unsigned int sh_hist[BINS];
    __shared__ float        sh_psum;

    const int tid = threadIdx.x;
    if (tid < BINS) sh_hist[tid] = 0u;
    if (tid == 0)   sh_psum = 0.0f;
    if (blockIdx.x == 0 && tid == 0) g_done = 0u;   // reset fuse counter
    __syncthreads();

    const int patch = blockIdx.x >> 5;     // 0..63
    const int chunk = blockIdx.x & (CHUNKS - 1);
    const int pr = patch >> 3;             // patch row (height)
    const int pc = patch & 7;              // patch col (width)
    const int warp = tid >> 5;
    const int lane = tid & 31;

    const size_t col = (size_t)pc * PW + (size_t)lane * 4;
    const int s0 = chunk * 8 + warp;
    float acc = 0.0f;

    #pragma unroll 2
    for (int i = 0; i < ITERS; i++) {
        const int s  = s0 + i * (CHUNKS * 8);
        const int bc = s >> 7;         // which (b,c) plane
        const int r  = s & 127;        // row within patch
        const size_t base =
            (((size_t)bc * IMG_H) + (size_t)pr * PH + r) * (size_t)IMG_W + col;

        const float4 h  = *reinterpret_cast<const float4*>(hr + base);
        const float4 sv = *reinterpret_cast<const float4*>(sr + base);

        // (h * 255.0f) f32 multiply, truncate toward zero — bit-identical to
        // (patches * 255.0).astype(int32). Values in [0,1) -> bins 0..254.
        int b0 = (int)(h.x * 255.0f);
        int b1 = (int)(h.y * 255.0f);
        int b2 = (int)(h.z * 255.0f);
        int b3 = (int)(h.w * 255.0f);

        atomicAdd(&sh_hist[b0], 1u);
        atomicAdd(&sh_hist[b1], 1u);
        atomicAdd(&sh_hist[b2], 1u);
        atomicAdd(&sh_hist[b3], 1u);

        acc += fabsf(sv.x - h.x) + fabsf(sv.y - h.y)
             + fabsf(sv.z - h.z) + fabsf(sv.w - h.w);
    }

    // warp tree-reduce abs-diff partial
    #pragma unroll
    for (int o = 16; o > 0; o >>= 1)
        acc += __shfl_down_sync(0xffffffffu, acc, o);
    if (lane == 0) atomicAdd(&sh_psum, acc);
    __syncthreads();

    // plain stores — no global atomics, no pre-zeroing required
    if (tid < BINS) g_hist_part[blockIdx.x * BINS + tid] = sh_hist[tid];
    if (tid == 0)   g_psum_part[blockIdx.x] = sh_psum;
}

// Per-element term — VALIDATED in R13 (do not change):
//   p = c * fl(1/786432); l2 = logf(p) * fl(1/ln2); term = p * l2
//   (separate f32 muls, no FMA); zero-count bins -> exact 0.0f.
__device__ __forceinline__ float ent_term(unsigned int c) {
    float pf   = __fmul_rn((float)c, RECIP_N);
    float safe = (c > 0u) ? pf : 1.0f;
    float l2   = __fmul_rn(logf(safe), RECIP_LN2);
    return (c > 0u) ? __fmul_rn(pf, l2) : 0.0f;
}

// Entropy (VALIDATED R13 association, bit-frozen) + fused loss stage:
// 64 blocks of 256 threads; the LAST block to finish entropy also computes
// the final loss (threadfence + atomic counter handshake).
__global__ __launch_bounds__(256)
void entropy_loss_kernel(float* __restrict__ out) {
    __shared__ float partials[8];
    const int p    = blockIdx.x;       // patch 0..63
    const int t    = threadIdx.x;      // 0..255 = bin
    const int lane = t & 31;
    const int warp = t >> 5;

    // exact integer merge of the 32 chunk partials (association-free)
    unsigned int c = 0u;
    const unsigned int* part = &g_hist_part[(p * CHUNKS) * BINS + t];
    #pragma unroll
    for (int k = 0; k < CHUNKS; k++)
        c += part[k * BINS];

    // flat 256-thread row reduce — bit-identical to reference
    float acc = __fadd_rn(0.0f, ent_term(c));
    #pragma unroll
    for (int o = 16; o > 0; o >>= 1)
        acc = __fadd_rn(acc, __shfl_down_sync(0xffffffffu, acc, o));
    if (lane == 0) partials[warp] = acc;
    __syncthreads();
    if (warp == 0) {
        float v = (lane < 8) ? partials[lane] : 0.0f;
        #pragma unroll
        for (int o = 16; o > 0; o >>= 1)
            v = __fadd_rn(v, __shfl_down_sync(0xffffffffu, v, o));
        if (lane == 0) g_ent[p] = -v;   // negate after the sum, like the ref
    }

    // ---- last-done block computes the loss ----
    __threadfence();
    __shared__ int is_last;
    if (t == 0) is_last = (atomicAdd(&g_done, 1u) == 63u) ? 1 : 0;
    __syncthreads();
    if (!is_last) return;

    __shared__ double Ssum[64];
    __shared__ float  ent[64];
    __shared__ float  red32[4];
    __shared__ double redd[2];

    // warp w reduces patches w, w+8, ..., w+56: lane l loads chunk-l partial
    for (int q = warp; q < 64; q += 8) {
        double v = (double)g_psum_part[q * CHUNKS + lane];
        #pragma unroll
        for (int o = 16; o > 0; o >>= 1)
            v += __shfl_down_sync(0xffffffffu, v, o);
        if (lane == 0) Ssum[q] = v;
    }
    if (t < 64) ent[t] = g_ent[t];
    __syncthreads();

    // parallel min/max over 64 entropies (order-independent)
    if (t < 64) {
        float mnv = ent[t], mxv = ent[t];
        #pragma unroll
        for (int o = 16; o > 0; o >>= 1) {
            mnv = fminf(mnv, __shfl_down_sync(0xffffffffu, mnv, o));
            mxv = fmaxf(mxv, __shfl_down_sync(0xffffffffu, mxv, o));
        }
        if (lane == 0) { red32[warp] = mnv; red32[warp + 2] = mxv; }
    }
    __syncthreads();
    __shared__ float s_mn, s_mx;
    if (t == 0) {
        s_mn = fminf(red32[0], red32[1]);
        s_mx = fmaxf(red32[2], red32[3]);
    }
    __syncthreads();
    const float mn = s_mn, mx = s_mx;

    // parallel weighted loss: sum_i w_i * S_i in f64
    if (t < 64) {
        // weight in f32 exactly as the reference map: (e - mn) / original max
        float w = __fdiv_rn(__fadd_rn(ent[t], -mn), mx);
        double prod = (double)w * Ssum[t];
        #pragma unroll
        for (int o = 16; o > 0; o >>= 1)
            prod += __shfl_down_sync(0xffffffffu, prod, o);
        if (lane == 0) redd[warp] = prod;
    }
    __syncthreads();
    if (t == 0)
        out[0] = (float)((redd[0] + redd[1]) / TOTAL_ELEMS);
}

extern "C" void kernel_launch(void* const* d_in, const int* in_sizes, int n_in,
                              void* d_out, int out_size) {
    const float* sr = (const float*)d_in[0];
    const float* hr = (const float*)d_in[1];
    float* out = (float*)d_out;
    (void)in_sizes; (void)n_in; (void)out_size;

    hist_kernel<<<NBLK, 256>>>(sr, hr);
    entropy_loss_kernel<<<64, 256>>>(out);
}

// round 17
// speedup vs baseline: 1.1456x; 1.0607x over previous
#include <cuda_runtime.h>
#include <math.h>

// Problem constants
#define NPATCH     8
#define BINS       256
#define IMG_H      1024
#define IMG_W      1024
#define NBC        48            // B*C = 16*3
#define PH         128           // patch height
#define PW         128           // patch width
#define SEGS       6144          // NBC * PH row-segments per patch
#define CHUNKS     32            // blocks per patch
#define NBLK       (64 * CHUNKS) // 2048 hist blocks
#define ITERS      (SEGS / (CHUNKS * 8))   // 24, uniform across warps
#define TOTAL_ELEMS 50331648.0   // 16*3*1024*1024

// XLA algsimp folds divide-by-constant -> multiply-by-f32-reciprocal.
__device__ __constant__ float RECIP_N   = 1.0f / 786432.0f;   // 0x35AAAAAB
__device__ __constant__ float RECIP_LN2 = 1.442695040888963f; // fl(1/fl(ln2)) = 0x3FB8AA3B

// Scratch (no allocation allowed in kernel_launch). Plain-store partials —
// every slot is overwritten each run, so NO zero kernel is needed.
__device__ unsigned int g_hist_part[NBLK * BINS];   // 2 MB, L2-resident
__device__ float        g_psum_part[NBLK];
__device__ float        g_ent[64];

// One block = (patch, chunk). 256 threads, 8 warps.
// Each warp processes whole 128-float row segments: lane -> float4.
// __ldcs: sr/hr are read-once -> evict-first, keep L2 for partials.
__global__ __launch_bounds__(256)
void hist_kernel(const float* __restrict__ sr, const float* __restrict__ hr) {
    __shared__ unsigned int sh_hist[BINS];
    __shared__ float        sh_psum;

    const int tid = threadIdx.x;
    if (tid < BINS) sh_hist[tid] = 0u;
    if (tid == 0)   sh_psum = 0.0f;
    __syncthreads();

    const int patch = blockIdx.x >> 5;     // 0..63
    const int chunk = blockIdx.x & (CHUNKS - 1);
    const int pr = patch >> 3;             // patch row (height)
    const int pc = patch & 7;              // patch col (width)
    const int warp = tid >> 5;
    const int lane = tid & 31;

    const size_t col = (size_t)pc * PW + (size_t)lane * 4;
    const int s0 = chunk * 8 + warp;
    float acc = 0.0f;

    #pragma unroll 2
    for (int i = 0; i < ITERS; i++) {
        const int s  = s0 + i * (CHUNKS * 8);
        const int bc = s >> 7;         // which (b,c) plane
        const int r  = s & 127;        // row within patch
        const size_t base =
            (((size_t)bc * IMG_H) + (size_t)pr * PH + r) * (size_t)IMG_W + col;

        const float4 h  = __ldcs(reinterpret_cast<const float4*>(hr + base));
        const float4 sv = __ldcs(reinterpret_cast<const float4*>(sr + base));

        // (h * 255.0f) f32 multiply, truncate toward zero — bit-identical to
        // (patches * 255.0).astype(int32). Values in [0,1) -> bins 0..254.
        int b0 = (int)(h.x * 255.0f);
        int b1 = (int)(h.y * 255.0f);
        int b2 = (int)(h.z * 255.0f);
        int b3 = (int)(h.w * 255.0f);

        atomicAdd(&sh_hist[b0], 1u);
        atomicAdd(&sh_hist[b1], 1u);
        atomicAdd(&sh_hist[b2], 1u);
        atomicAdd(&sh_hist[b3], 1u);

        acc += fabsf(sv.x - h.x) + fabsf(sv.y - h.y)
             + fabsf(sv.z - h.z) + fabsf(sv.w - h.w);
    }

    // warp tree-reduce abs-diff partial
    #pragma unroll
    for (int o = 16; o > 0; o >>= 1)
        acc += __shfl_down_sync(0xffffffffu, acc, o);
    if (lane == 0) atomicAdd(&sh_psum, acc);
    __syncthreads();

    // plain stores — no global atomics, no pre-zeroing required
    if (tid < BINS) g_hist_part[blockIdx.x * BINS + tid] = sh_hist[tid];
    if (tid == 0)   g_psum_part[blockIdx.x] = sh_psum;
}

// Per-element term — VALIDATED in R13 (do not change):
//   p = c * fl(1/786432); l2 = logf(p) * fl(1/ln2); term = p * l2
//   (separate f32 muls, no FMA); zero-count bins -> exact 0.0f.
__device__ __forceinline__ float ent_term(unsigned int c) {
    float pf   = __fmul_rn((float)c, RECIP_N);
    float safe = (c > 0u) ? pf : 1.0f;
    float l2   = __fmul_rn(logf(safe), RECIP_LN2);
    return (c > 0u) ? __fmul_rn(pf, l2) : 0.0f;
}

__device__ unsigned int g_done2;

// Entropy + fused loss: 64 blocks x 1024 threads.
// Chunk merge is 4-way parallel (quarter q sums 8 chunk partials; exact
// integer smem combine — association-free), then the VALIDATED R13
// flat-256 tree runs on threads t<256 exactly as before (bit-frozen).
// Last-done block computes the loss stage.
__global__ __launch_bounds__(1024)
void entropy_loss_kernel(float* __restrict__ out) {
    __shared__ unsigned int cpart[4][BINS];
    __shared__ float partials[8];

    const int p    = blockIdx.x;       // patch 0..63
    const int t    = threadIdx.x;      // 0..1023
    const int lane = t & 31;
    const int warp = t >> 5;           // 0..31
    const int q    = t >> 8;           // quarter 0..3
    const int bin  = t & 255;

    if (p == 0 && t == 0) {
        // reset handled below via separate counter scheme (see g_done2 note)
    }

    // 4-way parallel chunk merge: quarter q sums chunks 8q..8q+7
    unsigned int cq = 0u;
    {
        const unsigned int* part =
            &g_hist_part[(p * CHUNKS + q * 8) * BINS + bin];
        #pragma unroll
        for (int k = 0; k < 8; k++)
            cq += part[k * BINS];
    }
    cpart[q][bin] = cq;
    __syncthreads();

    if (t < BINS) {
        unsigned int c = cpart[0][t] + cpart[1][t] + cpart[2][t] + cpart[3][t];

        // flat 256-thread row reduce — bit-identical to reference (frozen)
        float acc = __fadd_rn(0.0f, ent_term(c));
        #pragma unroll
        for (int o = 16; o > 0; o >>= 1)
            acc = __fadd_rn(acc, __shfl_down_sync(0xffffffffu, acc, o));
        if (lane == 0) partials[warp] = acc;
    }
    __syncthreads();
    if (warp == 0) {
        float v = (lane < 8) ? partials[lane] : 0.0f;
        #pragma unroll
        for (int o = 16; o > 0; o >>= 1)
            v = __fadd_rn(v, __shfl_down_sync(0xffffffffu, v, o));
        if (lane == 0) g_ent[p] = -v;   // negate after the sum, like the ref
    }

    // ---- last-done block computes the loss ----
    __threadfence();
    __shared__ int is_last;
    if (t == 0) {
        // counter cycles 0..63 then wraps to 0 for the next graph replay:
        // atomicInc with bound 63 resets automatically.
        is_last = (atomicInc(&g_done2, 63u) == 63u) ? 1 : 0;
    }
    __syncthreads();
    if (!is_last) return;

    __shared__ double Ssum[64];
    __shared__ float  ent[64];
    __shared__ float  red32[4];
    __shared__ double redd[2];

    // warp w (0..31) reduces patches w and w+32
    {
        const int pq = warp;
        double v = (double)g_psum_part[pq * CHUNKS + lane];
        #pragma unroll
        for (int o = 16; o > 0; o >>= 1)
            v += __shfl_down_sync(0xffffffffu, v, o);
        if (lane == 0) Ssum[pq] = v;
        const int p2 = warp + 32;
        double v2 = (double)g_psum_part[p2 * CHUNKS + lane];
        #pragma unroll
        for (int o = 16; o > 0; o >>= 1)
            v2 += __shfl_down_sync(0xffffffffu, v2, o);
        if (lane == 0) Ssum[p2] = v2;
    }
    if (t < 64) ent[t] = g_ent[t];
    __syncthreads();

    // parallel min/max over 64 entropies (order-independent)
    if (t < 64) {
        float mnv = ent[t], mxv = ent[t];
        #pragma unroll
        for (int o = 16; o > 0; o >>= 1) {
            mnv = fminf(mnv, __shfl_down_sync(0xffffffffu, mnv, o));
            mxv = fmaxf(mxv, __shfl_down_sync(0xffffffffu, mxv, o));
        }
        if (lane == 0) { red32[warp] = mnv; red32[warp + 2] = mxv; }
    }
    __syncthreads();
    __shared__ float s_mn, s_mx;
    if (t == 0) {
        s_mn = fminf(red32[0], red32[1]);
        s_mx = fmaxf(red32[2], red32[3]);
    }
    __syncthreads();
    const float mn = s_mn, mx = s_mx;

    // parallel weighted loss: sum_i w_i * S_i in f64
    if (t < 64) {
        // weight in f32 exactly as the reference map: (e - mn) / original max
        float w = __fdiv_rn(__fadd_rn(ent[t], -mn), mx);
        double prod = (double)w * Ssum[t];
        #pragma unroll
        for (int o = 16; o > 0; o >>= 1)
            prod += __shfl_down_sync(0xffffffffu, prod, o);
        if (lane == 0) redd[warp] = prod;
    }
    __syncthreads();
    if (t == 0)
        out[0] = (float)((redd[0] + redd[1]) / TOTAL_ELEMS);
}

extern "C" void kernel_launch(void* const* d_in, const int* in_sizes, int n_in,
                              void* d_out, int out_size) {
    const float* sr = (const float*)d_in[0];
    const float* hr = (const float*)d_in[1];
    float* out = (float*)d_out;
    (void)in_sizes; (void)n_in; (void)out_size;

    hist_kernel<<<NBLK, 256>>>(sr, hr);
    entropy_loss_kernel<<<64, 1024>>>(out);
}